// round 10
// baseline (speedup 1.0000x reference)
#include <cuda_runtime.h>
#include <cstdint>
#include <cstddef>

#define BSZ  16384
#define SDIM 1024
#define ADIM 64
#define HID  1024
#define REC  1024
#define LATD 1024

// Scratch
__device__ float g_x [(size_t)BSZ * HID];
__device__ float g_gi[(size_t)BSZ * 3 * REC];
__device__ float g_gh[(size_t)BSZ * 3 * REC];

// ---- ambiguous-group fix machinery ----
#define FIX_TAU  2e-4f
#define AMB_CAP  16384
#define FIX_ROWS 512
__device__ int   g_namb;
__device__ int   g_nrows;
__device__ int   g_amb[AMB_CAP];
__device__ int   g_rowlist[FIX_ROWS];
__device__ int   g_rowflag[BSZ];
__device__ float g_fin [(size_t)FIX_ROWS * 1088];
__device__ float g_fdet[(size_t)FIX_ROWS * 1024];
__device__ float g_fobs[(size_t)FIX_ROWS * 1024];
__device__ float g_fx  [(size_t)FIX_ROWS * 1024];
__device__ float g_fgi [(size_t)FIX_ROWS * 3072];
__device__ float g_fgh [(size_t)FIX_ROWS * 3072];
__device__ float g_fh  [(size_t)FIX_ROWS * 1024];
__device__ float g_flog[(size_t)FIX_ROWS * 1024];

__device__ __forceinline__ uint32_t smem_u32(const void* p) {
    uint32_t a;
    asm("{ .reg .u64 t; cvta.to.shared.u64 t, %1; cvt.u32.u64 %0, t; }"
        : "=r"(a) : "l"(p));
    return a;
}

// ---------------- bf16x2-split mma.sync GEMM, producer-side split ----------------
// CTA 128x64 tile, 256 thr (8 warps 4x2), warp tile 32x32, K-chunk 32.
// 2 CTAs/SM (regs+smem sized for it) so LDS/STS bursts of one CTA overlap
// the mma bursts of the other.
#define MMA_THR 256
#define WSTR 20
#define TILE_AW (128 * WSTR)                  // 2560 words
#define TILE_BW (64 * WSTR)                   // 1280 words
#define STG_W   (2 * (TILE_AW + TILE_BW))     // 7680 words per stage
#define STG_BYTES (STG_W * 4)                 // 30720
#define SMEM_CA  (2 * STG_BYTES)              // 61440
// word offsets inside a stage
#define OFF_AH 0
#define OFF_AL TILE_AW
#define OFF_BH (2 * TILE_AW)
#define OFF_BL (2 * TILE_AW + TILE_BW)

__device__ __forceinline__ void mma16(float c[4], const uint32_t a[4], const uint32_t b[2]) {
    asm volatile("mma.sync.aligned.m16n8k16.row.col.f32.bf16.bf16.f32 "
                 "{%0,%1,%2,%3}, {%4,%5,%6,%7}, {%8,%9}, {%0,%1,%2,%3};"
                 : "+f"(c[0]), "+f"(c[1]), "+f"(c[2]), "+f"(c[3])
                 : "r"(a[0]), "r"(a[1]), "r"(a[2]), "r"(a[3]), "r"(b[0]), "r"(b[1]));
}
__device__ __forceinline__ void splitbf(float x0, float x1, uint32_t& hi, uint32_t& lo) {
    uint32_t u0 = __float_as_uint(x0), u1 = __float_as_uint(x1);
    uint32_t h;
    asm("prmt.b32 %0, %1, %2, 0x7632;" : "=r"(h) : "r"(u0), "r"(u1));
    hi = h;
    float f0 = __uint_as_float(u0 & 0xFFFF0000u);
    float f1 = __uint_as_float(u1 & 0xFFFF0000u);
    float r0 = x0 - f0;
    float r1 = x1 - f1;
    asm("cvt.rn.bf16x2.f32 %0, %1, %2;" : "=r"(lo) : "f"(r1), "f"(r0));
}
__device__ __forceinline__ void sts128(uint32_t addr, uint32_t a, uint32_t b,
                                       uint32_t c, uint32_t d) {
    asm volatile("st.shared.v4.b32 [%0], {%1,%2,%3,%4};"
                 :: "r"(addr), "r"(a), "r"(b), "r"(c), "r"(d) : "memory");
}

__global__ __launch_bounds__(MMA_THR, 2)
void mma_gemm(const float* __restrict__ A1, int K1,
              const float* __restrict__ A2, int K2,
              const unsigned char* __restrict__ mask,
              const float* __restrict__ B,
              const float* __restrict__ bias,
              float* __restrict__ C, int Ntot)
{
    extern __shared__ __align__(16) float sm[];
    const uint32_t sbase = smem_u32(sm);

    const int K  = K1 + K2;
    const int KC = K >> 5;
    const int bm = blockIdx.y << 7;
    const int bn = blockIdx.x << 6;
    const int t  = threadIdx.x;
    const int wid  = t >> 5;
    const int lane = t & 31;
    const int g = lane >> 2;
    const int c = lane & 3;
    const int wm = (wid >> 1) << 5;   // 0,32,64,96
    const int wn = (wid & 1) << 5;    // 0,32

    // copy mapping: A row = t>>1 (0..127), 16 k at kqA; B row = t>>2 (0..63), 8 k at kqB
    const int rowA = t >> 1;
    const int kqA  = (t & 1) << 4;
    const int rowB = t >> 2;
    const int kqB  = (t & 3) << 3;
    const bool masked = (mask != nullptr) && mask[bm + rowA];

    float4 ar[4], br[2];

    auto ldg = [&](int kc) {
        const int kg = (kc << 5) + kqA;
        if (kg < K1) {
            if (masked) {
#pragma unroll
                for (int i = 0; i < 4; i++) ar[i] = make_float4(0.f, 0.f, 0.f, 0.f);
            } else {
                const float* p = A1 + (size_t)(bm + rowA) * K1 + kg;
#pragma unroll
                for (int i = 0; i < 4; i++) ar[i] = *reinterpret_cast<const float4*>(p + i * 4);
            }
        } else {
            const float* p = A2 + (size_t)(bm + rowA) * K2 + (kg - K1);
#pragma unroll
            for (int i = 0; i < 4; i++) ar[i] = *reinterpret_cast<const float4*>(p + i * 4);
        }
        const int kgb = (kc << 5) + kqB;
        const float* q = B + (size_t)(bn + rowB) * K + kgb;
        br[0] = *reinterpret_cast<const float4*>(q);
        br[1] = *reinterpret_cast<const float4*>(q + 4);
    };

    auto sts = [&](int buf) {
        const uint32_t base = sbase + (uint32_t)buf * STG_BYTES;
        // A: 16 floats -> 8 hi + 8 lo words, 2 STS.128 each
        uint32_t h[8], l[8];
#pragma unroll
        for (int i = 0; i < 4; i++) {
            splitbf(ar[i].x, ar[i].y, h[i * 2], l[i * 2]);
            splitbf(ar[i].z, ar[i].w, h[i * 2 + 1], l[i * 2 + 1]);
        }
        const uint32_t aoff = (uint32_t)(rowA * WSTR + (kqA >> 1)) * 4u;
        sts128(base + OFF_AH * 4u + aoff, h[0], h[1], h[2], h[3]);
        sts128(base + OFF_AH * 4u + aoff + 16u, h[4], h[5], h[6], h[7]);
        sts128(base + OFF_AL * 4u + aoff, l[0], l[1], l[2], l[3]);
        sts128(base + OFF_AL * 4u + aoff + 16u, l[4], l[5], l[6], l[7]);
        // B: 8 floats -> 4 hi + 4 lo words
        uint32_t bh[4], bl[4];
        splitbf(br[0].x, br[0].y, bh[0], bl[0]);
        splitbf(br[0].z, br[0].w, bh[1], bl[1]);
        splitbf(br[1].x, br[1].y, bh[2], bl[2]);
        splitbf(br[1].z, br[1].w, bh[3], bl[3]);
        const uint32_t boff = (uint32_t)(rowB * WSTR + (kqB >> 1)) * 4u;
        sts128(base + OFF_BH * 4u + boff, bh[0], bh[1], bh[2], bh[3]);
        sts128(base + OFF_BL * 4u + boff, bl[0], bl[1], bl[2], bl[3]);
    };

    float acc[2][4][4];
#pragma unroll
    for (int i = 0; i < 2; i++)
#pragma unroll
        for (int j = 0; j < 4; j++)
#pragma unroll
            for (int r = 0; r < 4; r++) acc[i][j][r] = 0.f;

    ldg(0); sts(0);
    __syncthreads();
    ldg(1);

    const uint32_t* smw = reinterpret_cast<const uint32_t*>(sm);

    for (int k = 0; k < KC; k++) {
        if (k + 1 < KC) sts((k + 1) & 1);

        const uint32_t* S  = smw + (size_t)(k & 1) * STG_W;
        const uint32_t* AH = S + OFF_AH;
        const uint32_t* AL = S + OFF_AL;
        const uint32_t* BH = S + OFF_BH;
        const uint32_t* BL = S + OFF_BL;

#pragma unroll
        for (int ks = 0; ks < 2; ks++) {
            const int kb2 = ks << 3;
            uint32_t aH[2][4], aL[2][4], bH[4][2], bL[4][2];
#pragma unroll
            for (int i = 0; i < 2; i++) {
                int r0 = (wm + (i << 4) + g) * WSTR + kb2 + c;
                int r1 = r0 + 8 * WSTR;
                aH[i][0] = AH[r0];     aH[i][1] = AH[r1];
                aH[i][2] = AH[r0 + 4]; aH[i][3] = AH[r1 + 4];
                aL[i][0] = AL[r0];     aL[i][1] = AL[r1];
                aL[i][2] = AL[r0 + 4]; aL[i][3] = AL[r1 + 4];
            }
#pragma unroll
            for (int j = 0; j < 4; j++) {
                int r0 = (wn + (j << 3) + g) * WSTR + kb2 + c;
                bH[j][0] = BH[r0]; bH[j][1] = BH[r0 + 4];
                bL[j][0] = BL[r0]; bL[j][1] = BL[r0 + 4];
            }
#pragma unroll
            for (int i = 0; i < 2; i++)
#pragma unroll
                for (int j = 0; j < 4; j++) mma16(acc[i][j], aH[i], bH[j]);
#pragma unroll
            for (int i = 0; i < 2; i++)
#pragma unroll
                for (int j = 0; j < 4; j++) mma16(acc[i][j], aL[i], bH[j]);
#pragma unroll
            for (int i = 0; i < 2; i++)
#pragma unroll
                for (int j = 0; j < 4; j++) mma16(acc[i][j], aH[i], bL[j]);
        }
        if (k + 2 < KC) ldg(k + 2);
        __syncthreads();
    }

#pragma unroll
    for (int i = 0; i < 2; i++) {
        int row0 = bm + wm + (i << 4) + g;
        int row1 = row0 + 8;
#pragma unroll
        for (int j = 0; j < 4; j++) {
            int col = bn + wn + (j << 3) + (c << 1);
            float2 b2 = *reinterpret_cast<const float2*>(bias + col);
            float2 v0 = make_float2(acc[i][j][0] + b2.x, acc[i][j][1] + b2.y);
            float2 v1 = make_float2(acc[i][j][2] + b2.x, acc[i][j][3] + b2.y);
            *reinterpret_cast<float2*>(C + (size_t)row0 * Ntot + col) = v0;
            *reinterpret_cast<float2*>(C + (size_t)row1 * Ntot + col) = v1;
        }
    }
}

// ---------------- fp32 FFMA GEMM (fix path) ----------------
#define GBM 128
#define GBN 128
#define GBK 16
#define GTM 8
#define GTN 8

__global__ __launch_bounds__(256, 2)
void gemm_f32(const float* __restrict__ A1, int K1,
              const float* __restrict__ A2, int K2,
              const float* __restrict__ B,
              const float* __restrict__ bias,
              float* __restrict__ C, int N)
{
    __shared__ __align__(16) float As[GBK][GBM];
    __shared__ __align__(16) float Bs[GBK][GBN];
    const int K  = K1 + K2;
    const int bm = blockIdx.y * GBM;
    const int bn = blockIdx.x * GBN;
    const int t  = threadIdx.x;
    const int tx = t & 15;
    const int ty = t >> 4;

    float acc[GTM][GTN];
#pragma unroll
    for (int i = 0; i < GTM; i++)
#pragma unroll
        for (int j = 0; j < GTN; j++) acc[i][j] = 0.f;

    for (int kt = 0; kt < K; kt += GBK) {
#pragma unroll
        for (int q = 0; q < 2; q++) {
            int li  = t * 2 + q;
            int row = li >> 2;
            int kq  = (li & 3) << 2;
            int kg  = kt + kq;
            {
                int m = bm + row;
                float4 v;
                if (kg < K1) v = *reinterpret_cast<const float4*>(A1 + (size_t)m * K1 + kg);
                else         v = *reinterpret_cast<const float4*>(A2 + (size_t)m * K2 + (kg - K1));
                As[kq + 0][row] = v.x; As[kq + 1][row] = v.y;
                As[kq + 2][row] = v.z; As[kq + 3][row] = v.w;
            }
            {
                int n = bn + row;
                float4 w = *reinterpret_cast<const float4*>(B + (size_t)n * K + kg);
                Bs[kq + 0][row] = w.x; Bs[kq + 1][row] = w.y;
                Bs[kq + 2][row] = w.z; Bs[kq + 3][row] = w.w;
            }
        }
        __syncthreads();
#pragma unroll
        for (int k = 0; k < GBK; k++) {
            float4 a0 = *reinterpret_cast<const float4*>(&As[k][ty * GTM]);
            float4 a1 = *reinterpret_cast<const float4*>(&As[k][ty * GTM + 4]);
            float4 b0 = *reinterpret_cast<const float4*>(&Bs[k][tx * GTN]);
            float4 b1 = *reinterpret_cast<const float4*>(&Bs[k][tx * GTN + 4]);
            float a[8] = {a0.x, a0.y, a0.z, a0.w, a1.x, a1.y, a1.z, a1.w};
            float b[8] = {b0.x, b0.y, b0.z, b0.w, b1.x, b1.y, b1.z, b1.w};
#pragma unroll
            for (int i = 0; i < GTM; i++)
#pragma unroll
                for (int j = 0; j < GTN; j++)
                    acc[i][j] = fmaf(a[i], b[j], acc[i][j]);
        }
        __syncthreads();
    }
#pragma unroll
    for (int i = 0; i < GTM; i++) {
        int m = bm + ty * GTM + i;
        float* crow = C + (size_t)m * N + bn + tx * GTN;
#pragma unroll
        for (int j = 0; j < GTN; j++)
            crow[j] = acc[i][j] + bias[bn + tx * GTN + j];
    }
}

// ---------------- GRU elementwise combine ----------------
__global__ void gru_kernel(const float* __restrict__ deter,
                           const unsigned char* __restrict__ first,
                           float* __restrict__ h_out)
{
    int i = blockIdx.x * blockDim.x + threadIdx.x;
    if (i >= BSZ * REC) return;
    int m = i >> 10;
    int n = i & 1023;
    size_t base = (size_t)m * (3 * REC) + n;
    float ir  = g_gi[base];
    float iz  = g_gi[base + REC];
    float i_n = g_gi[base + 2 * REC];
    float hr  = g_gh[base];
    float hz  = g_gh[base + REC];
    float h_n = g_gh[base + 2 * REC];
    float d = first[m] ? 0.f : deter[i];
    float r  = 1.f / (1.f + expf(-(ir + hr)));
    float z  = 1.f / (1.f + expf(-(iz + hz)));
    float nn = tanhf(i_n + r * h_n);
    h_out[i] = (1.f - z) * nn + z * d;
}

// ---------------- threefry2x32 + gumbel ----------------
__device__ __forceinline__ uint32_t threefry_bits(uint32_t x1in)
{
    const uint32_t ks0 = 0u;
    const uint32_t ks1 = 42u;
    const uint32_t ks2 = 0x1BD11BDAu ^ ks0 ^ ks1;
    uint32_t x0 = 0u + ks0;
    uint32_t x1 = x1in + ks1;
#define TF_R(r) { x0 += x1; x1 = __funnelshift_l(x1, x1, (r)); x1 ^= x0; }
    TF_R(13) TF_R(15) TF_R(26) TF_R(6)
    x0 += ks1; x1 += ks2 + 1u;
    TF_R(17) TF_R(29) TF_R(16) TF_R(24)
    x0 += ks2; x1 += ks0 + 2u;
    TF_R(13) TF_R(15) TF_R(26) TF_R(6)
    x0 += ks0; x1 += ks1 + 3u;
    TF_R(17) TF_R(29) TF_R(16) TF_R(24)
    x0 += ks1; x1 += ks2 + 4u;
    TF_R(13) TF_R(15) TF_R(26) TF_R(6)
    x0 += ks2; x1 += ks0 + 5u;
#undef TF_R
    return x0 ^ x1;
}

__device__ __forceinline__ float gumbel_at(uint32_t idx)
{
    uint32_t bits = threefry_bits(idx);
    float f = __uint_as_float((bits >> 9) | 0x3f800000u) - 1.0f;
    float u = fmaxf(f, 1.17549435e-38f);
    float inner = -logf(u);
    return -__logf(inner);
}

__global__ void sample_kernel(const float* __restrict__ logits,
                              float* __restrict__ stoch_out)
{
    int g = blockIdx.x * blockDim.x + threadIdx.x;
    if (g >= BSZ * 32) return;
    const float4* lrow = reinterpret_cast<const float4*>(logits + (size_t)g * 32);
    float best = -3.4e38f, second = -3.4e38f;
    int   bi   = 0;
    uint32_t base = (uint32_t)g * 32u;
#pragma unroll
    for (int q = 0; q < 8; q++) {
        float4 lv = lrow[q];
        float l4[4] = {lv.x, lv.y, lv.z, lv.w};
#pragma unroll
        for (int ci = 0; ci < 4; ci++) {
            int d = q * 4 + ci;
            float s = l4[ci] + gumbel_at(base + (uint32_t)d);
            if (s > best) { second = best; best = s; bi = d; }
            else if (s > second) second = s;
        }
    }
    float4* dst = reinterpret_cast<float4*>(stoch_out + (size_t)g * 32);
#pragma unroll
    for (int q = 0; q < 8; q++) {
        float4 v;
        v.x = (bi == q * 4 + 0) ? 1.f : 0.f;
        v.y = (bi == q * 4 + 1) ? 1.f : 0.f;
        v.z = (bi == q * 4 + 2) ? 1.f : 0.f;
        v.w = (bi == q * 4 + 3) ? 1.f : 0.f;
        dst[q] = v;
    }
    if (best - second < FIX_TAU) {
        int slot = atomicAdd(&g_namb, 1);
        if (slot < AMB_CAP) g_amb[slot] = g;
    }
}

// ---------------- fix path ----------------
__global__ void init_fix()
{
    int t = blockIdx.x * blockDim.x + threadIdx.x;
    if (t == 0) { g_namb = 0; g_nrows = 0; }
    for (int i = t; i < BSZ; i += gridDim.x * blockDim.x) g_rowflag[i] = 0;
}

__global__ void gather_rows(const float* __restrict__ stoch,
                            const float* __restrict__ deter,
                            const float* __restrict__ action,
                            const float* __restrict__ obs,
                            const unsigned char* __restrict__ first)
{
    __shared__ int s_row, s_slot;
    int namb = min(g_namb, AMB_CAP);
    for (int e = blockIdx.x; e < namb; e += gridDim.x) {
        if (threadIdx.x == 0) {
            int row = g_amb[e] >> 5;
            int slot = -1;
            if (atomicExch(&g_rowflag[row], 1) == 0) {
                int s = atomicAdd(&g_nrows, 1);
                if (s < FIX_ROWS) { g_rowlist[s] = row; slot = s; }
            }
            s_row = row; s_slot = slot;
        }
        __syncthreads();
        int slot = s_slot, row = s_row;
        if (slot >= 0) {
            bool f = first[row] != 0;
            for (int j = threadIdx.x; j < SDIM; j += blockDim.x)
                g_fin[(size_t)slot * 1088 + j] = f ? 0.f : stoch[(size_t)row * SDIM + j];
            for (int j = threadIdx.x; j < ADIM; j += blockDim.x)
                g_fin[(size_t)slot * 1088 + SDIM + j] = action[(size_t)row * ADIM + j];
            for (int j = threadIdx.x; j < REC; j += blockDim.x)
                g_fdet[(size_t)slot * 1024 + j] = f ? 0.f : deter[(size_t)row * REC + j];
            for (int j = threadIdx.x; j < HID; j += blockDim.x)
                g_fobs[(size_t)slot * 1024 + j] = obs[(size_t)row * HID + j];
        }
        __syncthreads();
    }
}

__global__ void fgru_kernel()
{
    int i = blockIdx.x * blockDim.x + threadIdx.x;
    if (i >= FIX_ROWS * 1024) return;
    int r = i >> 10, n = i & 1023;
    size_t base = (size_t)r * 3072 + n;
    float ir  = g_fgi[base];
    float iz  = g_fgi[base + 1024];
    float i_n = g_fgi[base + 2048];
    float hr  = g_fgh[base];
    float hz  = g_fgh[base + 1024];
    float h_n = g_fgh[base + 2048];
    float d = g_fdet[i];
    float rr = 1.f / (1.f + expf(-(ir + hr)));
    float zz = 1.f / (1.f + expf(-(iz + hz)));
    float nn = tanhf(i_n + rr * h_n);
    g_fh[i] = (1.f - zz) * nn + zz * d;
}

__global__ void fix_sample(float* __restrict__ stoch_out)
{
    int idx = blockIdx.x * blockDim.x + threadIdx.x;
    int r = idx >> 5, gl = idx & 31;
    if (r >= min(g_nrows, FIX_ROWS)) return;
    int row = g_rowlist[r];
    const float* l = g_flog + (size_t)r * 1024 + gl * 32;
    uint32_t base = ((uint32_t)row * 32u + (uint32_t)gl) * 32u;
    float best = -3.4e38f;
    int bi = 0;
#pragma unroll
    for (int d = 0; d < 32; d++) {
        float s = l[d] + gumbel_at(base + (uint32_t)d);
        if (s > best) { best = s; bi = d; }
    }
    float* dst = stoch_out + (size_t)row * 1024 + gl * 32;
#pragma unroll
    for (int d = 0; d < 32; d++) dst[d] = (d == bi) ? 1.f : 0.f;
}

// ---------------- launch ----------------
extern "C" void kernel_launch(void* const* d_in, const int* in_sizes, int n_in,
                              void* d_out, int out_size)
{
    (void)in_sizes; (void)n_in; (void)out_size;
    const float* stoch  = (const float*)d_in[0];
    const float* deter  = (const float*)d_in[1];
    const float* action = (const float*)d_in[3];
    const float* obs    = (const float*)d_in[4];
    const unsigned char* first = (const unsigned char*)d_in[5];
    const float* W_in   = (const float*)d_in[6];
    const float* b_in   = (const float*)d_in[7];
    const float* W_ih   = (const float*)d_in[8];
    const float* b_ih   = (const float*)d_in[9];
    const float* W_hh   = (const float*)d_in[10];
    const float* b_hh   = (const float*)d_in[11];
    const float* W_post = (const float*)d_in[14];
    const float* b_post = (const float*)d_in[15];

    float* out        = (float*)d_out;
    float* h_out      = out;
    float* stoch_out  = out + (size_t)BSZ * LATD;
    float* logits_out = out + 2 * (size_t)BSZ * LATD;

    float *xp, *gip, *ghp;
    float *fin, *fdet, *fobs, *fx, *fgi, *fgh, *fh, *flog;
    cudaGetSymbolAddress((void**)&xp,  g_x);
    cudaGetSymbolAddress((void**)&gip, g_gi);
    cudaGetSymbolAddress((void**)&ghp, g_gh);
    cudaGetSymbolAddress((void**)&fin,  g_fin);
    cudaGetSymbolAddress((void**)&fdet, g_fdet);
    cudaGetSymbolAddress((void**)&fobs, g_fobs);
    cudaGetSymbolAddress((void**)&fx,   g_fx);
    cudaGetSymbolAddress((void**)&fgi,  g_fgi);
    cudaGetSymbolAddress((void**)&fgh,  g_fgh);
    cudaGetSymbolAddress((void**)&fh,   g_fh);
    cudaGetSymbolAddress((void**)&flog, g_flog);

    cudaFuncSetAttribute(mma_gemm, cudaFuncAttributeMaxDynamicSharedMemorySize, SMEM_CA);

    dim3 thr(MMA_THR);

    init_fix<<<64, 256>>>();

    // ---- main bf16x2-split path ----
    mma_gemm<<<dim3(HID / 64, BSZ / 128), thr, SMEM_CA>>>(
        stoch, SDIM, action, ADIM, first, W_in, b_in, xp, HID);
    mma_gemm<<<dim3(3 * REC / 64, BSZ / 128), thr, SMEM_CA>>>(
        xp, HID, xp, 0, nullptr, W_ih, b_ih, gip, 3 * REC);
    mma_gemm<<<dim3(3 * REC / 64, BSZ / 128), thr, SMEM_CA>>>(
        deter, REC, deter, 0, first, W_hh, b_hh, ghp, 3 * REC);
    gru_kernel<<<(BSZ * REC) / 256, 256>>>(deter, first, h_out);
    mma_gemm<<<dim3(LATD / 64, BSZ / 128), thr, SMEM_CA>>>(
        h_out, REC, obs, HID, nullptr, W_post, b_post, logits_out, LATD);
    sample_kernel<<<(BSZ * 32) / 256, 256>>>(logits_out, stoch_out);

    // ---- fp32 fix path for near-tie groups ----
    gather_rows<<<256, 256>>>(stoch, deter, action, obs, first);
    gemm_f32<<<dim3(HID / GBN, FIX_ROWS / GBM), dim3(256)>>>(
        fin, 1088, fin, 0, W_in, b_in, fx, HID);
    gemm_f32<<<dim3(3 * REC / GBN, FIX_ROWS / GBM), dim3(256)>>>(
        fx, 1024, fx, 0, W_ih, b_ih, fgi, 3 * REC);
    gemm_f32<<<dim3(3 * REC / GBN, FIX_ROWS / GBM), dim3(256)>>>(
        fdet, 1024, fdet, 0, W_hh, b_hh, fgh, 3 * REC);
    fgru_kernel<<<(FIX_ROWS * 1024) / 256, 256>>>();
    gemm_f32<<<dim3(LATD / GBN, FIX_ROWS / GBM), dim3(256)>>>(
        fh, 1024, fobs, 1024, W_post, b_post, flog, LATD);
    fix_sample<<<(FIX_ROWS * 32) / 256, 256>>>(stoch_out);
}

// round 11
// speedup vs baseline: 1.1723x; 1.1723x over previous
#include <cuda_runtime.h>
#include <cstdint>
#include <cstddef>

#define BSZ  16384
#define SDIM 1024
#define ADIM 64
#define HID  1024
#define REC  1024
#define LATD 1024

// Scratch
__device__ float g_x [(size_t)BSZ * HID];
__device__ float g_gi[(size_t)BSZ * 3 * REC];
__device__ float g_gh[(size_t)BSZ * 3 * REC];

// ---- ambiguous-group fix machinery ----
#define FIX_TAU  2e-4f
#define AMB_CAP  16384
#define FIX_ROWS 512
__device__ int   g_namb;
__device__ int   g_nrows;
__device__ int   g_amb[AMB_CAP];
__device__ int   g_rowlist[FIX_ROWS];
__device__ int   g_rowflag[BSZ];
__device__ float g_fin [(size_t)FIX_ROWS * 1088];
__device__ float g_fdet[(size_t)FIX_ROWS * 1024];
__device__ float g_fobs[(size_t)FIX_ROWS * 1024];
__device__ float g_fx  [(size_t)FIX_ROWS * 1024];
__device__ float g_fgi [(size_t)FIX_ROWS * 3072];
__device__ float g_fgh [(size_t)FIX_ROWS * 3072];
__device__ float g_fh  [(size_t)FIX_ROWS * 1024];
__device__ float g_flog[(size_t)FIX_ROWS * 1024];

__device__ __forceinline__ uint32_t smem_u32(const void* p) {
    uint32_t a;
    asm("{ .reg .u64 t; cvta.to.shared.u64 t, %1; cvt.u32.u64 %0, t; }"
        : "=r"(a) : "l"(p));
    return a;
}

// ---------------- bf16x2-split mma.sync GEMM, swizzled smem ----------------
// CTA 128x128, 512 thr (16 warps 4x4), warp tile 32x32, K-chunk 32.
// Tile component = 128 rows x 16 words (bf16x2 along k), XOR swizzle:
//   word(r, kw) = r*16 + (kw ^ (((r>>1)&3)<<2))
// -> STS.128 and fragment LDS.32 both provably bank-conflict-free.
#define MMA_THR 512
#define COMP_W  (128 * 16)                    // 2048 words per component
#define STG_W   (4 * COMP_W)                  // 8192 words per stage
#define STG_BYTES (STG_W * 4)                 // 32768
#define SMEM_CA  (2 * STG_BYTES)              // 65536
#define OFF_AH 0
#define OFF_AL COMP_W
#define OFF_BH (2 * COMP_W)
#define OFF_BL (3 * COMP_W)

__device__ __forceinline__ void mma16(float c[4], const uint32_t a[4], const uint32_t b[2]) {
    asm volatile("mma.sync.aligned.m16n8k16.row.col.f32.bf16.bf16.f32 "
                 "{%0,%1,%2,%3}, {%4,%5,%6,%7}, {%8,%9}, {%0,%1,%2,%3};"
                 : "+f"(c[0]), "+f"(c[1]), "+f"(c[2]), "+f"(c[3])
                 : "r"(a[0]), "r"(a[1]), "r"(a[2]), "r"(a[3]), "r"(b[0]), "r"(b[1]));
}
__device__ __forceinline__ void splitbf(float x0, float x1, uint32_t& hi, uint32_t& lo) {
    uint32_t u0 = __float_as_uint(x0), u1 = __float_as_uint(x1);
    uint32_t h;
    asm("prmt.b32 %0, %1, %2, 0x7632;" : "=r"(h) : "r"(u0), "r"(u1));
    hi = h;
    float f0 = __uint_as_float(u0 & 0xFFFF0000u);
    float f1 = __uint_as_float(u1 & 0xFFFF0000u);
    float r0 = x0 - f0;
    float r1 = x1 - f1;
    asm("cvt.rn.bf16x2.f32 %0, %1, %2;" : "=r"(lo) : "f"(r1), "f"(r0));
}
__device__ __forceinline__ void sts128(uint32_t addr, uint32_t a, uint32_t b,
                                       uint32_t c, uint32_t d) {
    asm volatile("st.shared.v4.b32 [%0], {%1,%2,%3,%4};"
                 :: "r"(addr), "r"(a), "r"(b), "r"(c), "r"(d) : "memory");
}

__global__ __launch_bounds__(MMA_THR, 1)
void mma_gemm(const float* __restrict__ A1, int K1,
              const float* __restrict__ A2, int K2,
              const unsigned char* __restrict__ mask,
              const float* __restrict__ B,
              const float* __restrict__ bias,
              float* __restrict__ C, int Ntot)
{
    extern __shared__ __align__(16) float sm[];
    const uint32_t sbase = smem_u32(sm);

    const int K  = K1 + K2;
    const int KC = K >> 5;
    const int bm = blockIdx.y << 7;
    const int bn = blockIdx.x << 7;
    const int t  = threadIdx.x;
    const int wid  = t >> 5;
    const int lane = t & 31;
    const int g = lane >> 2;
    const int c = lane & 3;
    const int wm = (wid >> 2) << 5;   // 0,32,64,96
    const int wn = (wid & 3) << 5;    // 0,32,64,96

    // copy mapping: row = t>>2 (0..127), 8 k-elems at kq0 = (t&3)*8
    const int rowA = t >> 2;
    const int kq0  = (t & 3) << 3;
    const int kw0s = ((t & 3) << 2) ^ (((rowA >> 1) & 3) << 2);  // swizzled word off
    const bool masked = (mask != nullptr) && mask[bm + rowA];

    float4 ar0, ar1, br0, br1;

    auto ldg = [&](int kc) {
        const int kg = (kc << 5) + kq0;
        if (kg < K1) {
            if (masked) {
                ar0 = make_float4(0.f, 0.f, 0.f, 0.f);
                ar1 = ar0;
            } else {
                const float* p = A1 + (size_t)(bm + rowA) * K1 + kg;
                ar0 = *reinterpret_cast<const float4*>(p);
                ar1 = *reinterpret_cast<const float4*>(p + 4);
            }
        } else {
            const float* p = A2 + (size_t)(bm + rowA) * K2 + (kg - K1);
            ar0 = *reinterpret_cast<const float4*>(p);
            ar1 = *reinterpret_cast<const float4*>(p + 4);
        }
        const float* q = B + (size_t)(bn + rowA) * K + kg;
        br0 = *reinterpret_cast<const float4*>(q);
        br1 = *reinterpret_cast<const float4*>(q + 4);
    };

    auto sts = [&](int buf) {
        const uint32_t base = sbase + (uint32_t)buf * STG_BYTES;
        const uint32_t off = (uint32_t)(rowA * 16 + kw0s) * 4u;
        uint32_t h0, h1, h2, h3, l0, l1, l2, l3;
        splitbf(ar0.x, ar0.y, h0, l0); splitbf(ar0.z, ar0.w, h1, l1);
        splitbf(ar1.x, ar1.y, h2, l2); splitbf(ar1.z, ar1.w, h3, l3);
        sts128(base + OFF_AH * 4u + off, h0, h1, h2, h3);
        sts128(base + OFF_AL * 4u + off, l0, l1, l2, l3);
        splitbf(br0.x, br0.y, h0, l0); splitbf(br0.z, br0.w, h1, l1);
        splitbf(br1.x, br1.y, h2, l2); splitbf(br1.z, br1.w, h3, l3);
        sts128(base + OFF_BH * 4u + off, h0, h1, h2, h3);
        sts128(base + OFF_BL * 4u + off, l0, l1, l2, l3);
    };

    float acc[2][4][4];
#pragma unroll
    for (int i = 0; i < 2; i++)
#pragma unroll
        for (int j = 0; j < 4; j++)
#pragma unroll
            for (int r = 0; r < 4; r++) acc[i][j][r] = 0.f;

    ldg(0); sts(0);
    __syncthreads();
    ldg(1);

    const uint32_t* smw = reinterpret_cast<const uint32_t*>(sm);

    // per-lane swizzle for fragment loads: rows r=R0+g, swz depends only on g
    const int swzf = ((g >> 1) & 3) << 2;

    for (int k = 0; k < KC; k++) {
        if (k + 1 < KC) sts((k + 1) & 1);

        const uint32_t* S  = smw + (size_t)(k & 1) * STG_W;
        const uint32_t* AH = S + OFF_AH;
        const uint32_t* AL = S + OFF_AL;
        const uint32_t* BH = S + OFF_BH;
        const uint32_t* BL = S + OFF_BL;

#pragma unroll
        for (int ks = 0; ks < 2; ks++) {
            const int w0 = ((ks << 3) + c) ^ swzf;        // frag word 0
            const int w1 = ((ks << 3) + 4 + c) ^ swzf;    // frag word +4
            uint32_t aH[2][4], aL[2][4], bH[4][2], bL[4][2];
#pragma unroll
            for (int i = 0; i < 2; i++) {
                int r0 = (wm + (i << 4) + g) << 4;
                int r1 = r0 + (8 << 4);
                aH[i][0] = AH[r0 + w0]; aH[i][1] = AH[r1 + w0];
                aH[i][2] = AH[r0 + w1]; aH[i][3] = AH[r1 + w1];
                aL[i][0] = AL[r0 + w0]; aL[i][1] = AL[r1 + w0];
                aL[i][2] = AL[r0 + w1]; aL[i][3] = AL[r1 + w1];
            }
#pragma unroll
            for (int j = 0; j < 4; j++) {
                int r0 = (wn + (j << 3) + g) << 4;
                bH[j][0] = BH[r0 + w0]; bH[j][1] = BH[r0 + w1];
                bL[j][0] = BL[r0 + w0]; bL[j][1] = BL[r0 + w1];
            }
#pragma unroll
            for (int i = 0; i < 2; i++)
#pragma unroll
                for (int j = 0; j < 4; j++) mma16(acc[i][j], aH[i], bH[j]);
#pragma unroll
            for (int i = 0; i < 2; i++)
#pragma unroll
                for (int j = 0; j < 4; j++) mma16(acc[i][j], aL[i], bH[j]);
#pragma unroll
            for (int i = 0; i < 2; i++)
#pragma unroll
                for (int j = 0; j < 4; j++) mma16(acc[i][j], aH[i], bL[j]);
        }
        if (k + 2 < KC) ldg(k + 2);
        __syncthreads();
    }

#pragma unroll
    for (int i = 0; i < 2; i++) {
        int row0 = bm + wm + (i << 4) + g;
        int row1 = row0 + 8;
#pragma unroll
        for (int j = 0; j < 4; j++) {
            int col = bn + wn + (j << 3) + (c << 1);
            float2 b2 = *reinterpret_cast<const float2*>(bias + col);
            float2 v0 = make_float2(acc[i][j][0] + b2.x, acc[i][j][1] + b2.y);
            float2 v1 = make_float2(acc[i][j][2] + b2.x, acc[i][j][3] + b2.y);
            *reinterpret_cast<float2*>(C + (size_t)row0 * Ntot + col) = v0;
            *reinterpret_cast<float2*>(C + (size_t)row1 * Ntot + col) = v1;
        }
    }
}

// ---------------- fp32 FFMA GEMM (fix path) ----------------
#define GBM 128
#define GBN 128
#define GBK 16
#define GTM 8
#define GTN 8

__global__ __launch_bounds__(256, 2)
void gemm_f32(const float* __restrict__ A1, int K1,
              const float* __restrict__ A2, int K2,
              const float* __restrict__ B,
              const float* __restrict__ bias,
              float* __restrict__ C, int N)
{
    __shared__ __align__(16) float As[GBK][GBM];
    __shared__ __align__(16) float Bs[GBK][GBN];
    const int K  = K1 + K2;
    const int bm = blockIdx.y * GBM;
    const int bn = blockIdx.x * GBN;
    const int t  = threadIdx.x;
    const int tx = t & 15;
    const int ty = t >> 4;

    float acc[GTM][GTN];
#pragma unroll
    for (int i = 0; i < GTM; i++)
#pragma unroll
        for (int j = 0; j < GTN; j++) acc[i][j] = 0.f;

    for (int kt = 0; kt < K; kt += GBK) {
#pragma unroll
        for (int q = 0; q < 2; q++) {
            int li  = t * 2 + q;
            int row = li >> 2;
            int kq  = (li & 3) << 2;
            int kg  = kt + kq;
            {
                int m = bm + row;
                float4 v;
                if (kg < K1) v = *reinterpret_cast<const float4*>(A1 + (size_t)m * K1 + kg);
                else         v = *reinterpret_cast<const float4*>(A2 + (size_t)m * K2 + (kg - K1));
                As[kq + 0][row] = v.x; As[kq + 1][row] = v.y;
                As[kq + 2][row] = v.z; As[kq + 3][row] = v.w;
            }
            {
                int n = bn + row;
                float4 w = *reinterpret_cast<const float4*>(B + (size_t)n * K + kg);
                Bs[kq + 0][row] = w.x; Bs[kq + 1][row] = w.y;
                Bs[kq + 2][row] = w.z; Bs[kq + 3][row] = w.w;
            }
        }
        __syncthreads();
#pragma unroll
        for (int k = 0; k < GBK; k++) {
            float4 a0 = *reinterpret_cast<const float4*>(&As[k][ty * GTM]);
            float4 a1 = *reinterpret_cast<const float4*>(&As[k][ty * GTM + 4]);
            float4 b0 = *reinterpret_cast<const float4*>(&Bs[k][tx * GTN]);
            float4 b1 = *reinterpret_cast<const float4*>(&Bs[k][tx * GTN + 4]);
            float a[8] = {a0.x, a0.y, a0.z, a0.w, a1.x, a1.y, a1.z, a1.w};
            float b[8] = {b0.x, b0.y, b0.z, b0.w, b1.x, b1.y, b1.z, b1.w};
#pragma unroll
            for (int i = 0; i < GTM; i++)
#pragma unroll
                for (int j = 0; j < GTN; j++)
                    acc[i][j] = fmaf(a[i], b[j], acc[i][j]);
        }
        __syncthreads();
    }
#pragma unroll
    for (int i = 0; i < GTM; i++) {
        int m = bm + ty * GTM + i;
        float* crow = C + (size_t)m * N + bn + tx * GTN;
#pragma unroll
        for (int j = 0; j < GTN; j++)
            crow[j] = acc[i][j] + bias[bn + tx * GTN + j];
    }
}

// ---------------- GRU elementwise combine ----------------
__global__ void gru_kernel(const float* __restrict__ deter,
                           const unsigned char* __restrict__ first,
                           float* __restrict__ h_out)
{
    int i = blockIdx.x * blockDim.x + threadIdx.x;
    if (i >= BSZ * REC) return;
    int m = i >> 10;
    int n = i & 1023;
    size_t base = (size_t)m * (3 * REC) + n;
    float ir  = g_gi[base];
    float iz  = g_gi[base + REC];
    float i_n = g_gi[base + 2 * REC];
    float hr  = g_gh[base];
    float hz  = g_gh[base + REC];
    float h_n = g_gh[base + 2 * REC];
    float d = first[m] ? 0.f : deter[i];
    float r  = 1.f / (1.f + expf(-(ir + hr)));
    float z  = 1.f / (1.f + expf(-(iz + hz)));
    float nn = tanhf(i_n + r * h_n);
    h_out[i] = (1.f - z) * nn + z * d;
}

// ---------------- threefry2x32 + gumbel ----------------
__device__ __forceinline__ uint32_t threefry_bits(uint32_t x1in)
{
    const uint32_t ks0 = 0u;
    const uint32_t ks1 = 42u;
    const uint32_t ks2 = 0x1BD11BDAu ^ ks0 ^ ks1;
    uint32_t x0 = 0u + ks0;
    uint32_t x1 = x1in + ks1;
#define TF_R(r) { x0 += x1; x1 = __funnelshift_l(x1, x1, (r)); x1 ^= x0; }
    TF_R(13) TF_R(15) TF_R(26) TF_R(6)
    x0 += ks1; x1 += ks2 + 1u;
    TF_R(17) TF_R(29) TF_R(16) TF_R(24)
    x0 += ks2; x1 += ks0 + 2u;
    TF_R(13) TF_R(15) TF_R(26) TF_R(6)
    x0 += ks0; x1 += ks1 + 3u;
    TF_R(17) TF_R(29) TF_R(16) TF_R(24)
    x0 += ks1; x1 += ks2 + 4u;
    TF_R(13) TF_R(15) TF_R(26) TF_R(6)
    x0 += ks2; x1 += ks0 + 5u;
#undef TF_R
    return x0 ^ x1;
}

__device__ __forceinline__ float gumbel_at(uint32_t idx)
{
    uint32_t bits = threefry_bits(idx);
    float f = __uint_as_float((bits >> 9) | 0x3f800000u) - 1.0f;
    float u = fmaxf(f, 1.17549435e-38f);
    float inner = -logf(u);
    return -__logf(inner);
}

__global__ void sample_kernel(const float* __restrict__ logits,
                              float* __restrict__ stoch_out)
{
    int g = blockIdx.x * blockDim.x + threadIdx.x;
    if (g >= BSZ * 32) return;
    const float4* lrow = reinterpret_cast<const float4*>(logits + (size_t)g * 32);
    float best = -3.4e38f, second = -3.4e38f;
    int   bi   = 0;
    uint32_t base = (uint32_t)g * 32u;
#pragma unroll
    for (int q = 0; q < 8; q++) {
        float4 lv = lrow[q];
        float l4[4] = {lv.x, lv.y, lv.z, lv.w};
#pragma unroll
        for (int ci = 0; ci < 4; ci++) {
            int d = q * 4 + ci;
            float s = l4[ci] + gumbel_at(base + (uint32_t)d);
            if (s > best) { second = best; best = s; bi = d; }
            else if (s > second) second = s;
        }
    }
    float4* dst = reinterpret_cast<float4*>(stoch_out + (size_t)g * 32);
#pragma unroll
    for (int q = 0; q < 8; q++) {
        float4 v;
        v.x = (bi == q * 4 + 0) ? 1.f : 0.f;
        v.y = (bi == q * 4 + 1) ? 1.f : 0.f;
        v.z = (bi == q * 4 + 2) ? 1.f : 0.f;
        v.w = (bi == q * 4 + 3) ? 1.f : 0.f;
        dst[q] = v;
    }
    if (best - second < FIX_TAU) {
        int slot = atomicAdd(&g_namb, 1);
        if (slot < AMB_CAP) g_amb[slot] = g;
    }
}

// ---------------- fix path ----------------
__global__ void init_fix()
{
    int t = blockIdx.x * blockDim.x + threadIdx.x;
    if (t == 0) { g_namb = 0; g_nrows = 0; }
    for (int i = t; i < BSZ; i += gridDim.x * blockDim.x) g_rowflag[i] = 0;
}

__global__ void gather_rows(const float* __restrict__ stoch,
                            const float* __restrict__ deter,
                            const float* __restrict__ action,
                            const float* __restrict__ obs,
                            const unsigned char* __restrict__ first)
{
    __shared__ int s_row, s_slot;
    int namb = min(g_namb, AMB_CAP);
    for (int e = blockIdx.x; e < namb; e += gridDim.x) {
        if (threadIdx.x == 0) {
            int row = g_amb[e] >> 5;
            int slot = -1;
            if (atomicExch(&g_rowflag[row], 1) == 0) {
                int s = atomicAdd(&g_nrows, 1);
                if (s < FIX_ROWS) { g_rowlist[s] = row; slot = s; }
            }
            s_row = row; s_slot = slot;
        }
        __syncthreads();
        int slot = s_slot, row = s_row;
        if (slot >= 0) {
            bool f = first[row] != 0;
            for (int j = threadIdx.x; j < SDIM; j += blockDim.x)
                g_fin[(size_t)slot * 1088 + j] = f ? 0.f : stoch[(size_t)row * SDIM + j];
            for (int j = threadIdx.x; j < ADIM; j += blockDim.x)
                g_fin[(size_t)slot * 1088 + SDIM + j] = action[(size_t)row * ADIM + j];
            for (int j = threadIdx.x; j < REC; j += blockDim.x)
                g_fdet[(size_t)slot * 1024 + j] = f ? 0.f : deter[(size_t)row * REC + j];
            for (int j = threadIdx.x; j < HID; j += blockDim.x)
                g_fobs[(size_t)slot * 1024 + j] = obs[(size_t)row * HID + j];
        }
        __syncthreads();
    }
}

__global__ void fgru_kernel()
{
    int i = blockIdx.x * blockDim.x + threadIdx.x;
    if (i >= FIX_ROWS * 1024) return;
    int r = i >> 10, n = i & 1023;
    size_t base = (size_t)r * 3072 + n;
    float ir  = g_fgi[base];
    float iz  = g_fgi[base + 1024];
    float i_n = g_fgi[base + 2048];
    float hr  = g_fgh[base];
    float hz  = g_fgh[base + 1024];
    float h_n = g_fgh[base + 2048];
    float d = g_fdet[i];
    float rr = 1.f / (1.f + expf(-(ir + hr)));
    float zz = 1.f / (1.f + expf(-(iz + hz)));
    float nn = tanhf(i_n + rr * h_n);
    g_fh[i] = (1.f - zz) * nn + zz * d;
}

__global__ void fix_sample(float* __restrict__ stoch_out)
{
    int idx = blockIdx.x * blockDim.x + threadIdx.x;
    int r = idx >> 5, gl = idx & 31;
    if (r >= min(g_nrows, FIX_ROWS)) return;
    int row = g_rowlist[r];
    const float* l = g_flog + (size_t)r * 1024 + gl * 32;
    uint32_t base = ((uint32_t)row * 32u + (uint32_t)gl) * 32u;
    float best = -3.4e38f;
    int bi = 0;
#pragma unroll
    for (int d = 0; d < 32; d++) {
        float s = l[d] + gumbel_at(base + (uint32_t)d);
        if (s > best) { best = s; bi = d; }
    }
    float* dst = stoch_out + (size_t)row * 1024 + gl * 32;
#pragma unroll
    for (int d = 0; d < 32; d++) dst[d] = (d == bi) ? 1.f : 0.f;
}

// ---------------- launch ----------------
extern "C" void kernel_launch(void* const* d_in, const int* in_sizes, int n_in,
                              void* d_out, int out_size)
{
    (void)in_sizes; (void)n_in; (void)out_size;
    const float* stoch  = (const float*)d_in[0];
    const float* deter  = (const float*)d_in[1];
    const float* action = (const float*)d_in[3];
    const float* obs    = (const float*)d_in[4];
    const unsigned char* first = (const unsigned char*)d_in[5];
    const float* W_in   = (const float*)d_in[6];
    const float* b_in   = (const float*)d_in[7];
    const float* W_ih   = (const float*)d_in[8];
    const float* b_ih   = (const float*)d_in[9];
    const float* W_hh   = (const float*)d_in[10];
    const float* b_hh   = (const float*)d_in[11];
    const float* W_post = (const float*)d_in[14];
    const float* b_post = (const float*)d_in[15];

    float* out        = (float*)d_out;
    float* h_out      = out;
    float* stoch_out  = out + (size_t)BSZ * LATD;
    float* logits_out = out + 2 * (size_t)BSZ * LATD;

    float *xp, *gip, *ghp;
    float *fin, *fdet, *fobs, *fx, *fgi, *fgh, *fh, *flog;
    cudaGetSymbolAddress((void**)&xp,  g_x);
    cudaGetSymbolAddress((void**)&gip, g_gi);
    cudaGetSymbolAddress((void**)&ghp, g_gh);
    cudaGetSymbolAddress((void**)&fin,  g_fin);
    cudaGetSymbolAddress((void**)&fdet, g_fdet);
    cudaGetSymbolAddress((void**)&fobs, g_fobs);
    cudaGetSymbolAddress((void**)&fx,   g_fx);
    cudaGetSymbolAddress((void**)&fgi,  g_fgi);
    cudaGetSymbolAddress((void**)&fgh,  g_fgh);
    cudaGetSymbolAddress((void**)&fh,   g_fh);
    cudaGetSymbolAddress((void**)&flog, g_flog);

    cudaFuncSetAttribute(mma_gemm, cudaFuncAttributeMaxDynamicSharedMemorySize, SMEM_CA);

    dim3 thr(MMA_THR);

    init_fix<<<64, 256>>>();

    // ---- main bf16x2-split path ----
    mma_gemm<<<dim3(HID / 128, BSZ / 128), thr, SMEM_CA>>>(
        stoch, SDIM, action, ADIM, first, W_in, b_in, xp, HID);
    mma_gemm<<<dim3(3 * REC / 128, BSZ / 128), thr, SMEM_CA>>>(
        xp, HID, xp, 0, nullptr, W_ih, b_ih, gip, 3 * REC);
    mma_gemm<<<dim3(3 * REC / 128, BSZ / 128), thr, SMEM_CA>>>(
        deter, REC, deter, 0, first, W_hh, b_hh, ghp, 3 * REC);
    gru_kernel<<<(BSZ * REC) / 256, 256>>>(deter, first, h_out);
    mma_gemm<<<dim3(LATD / 128, BSZ / 128), thr, SMEM_CA>>>(
        h_out, REC, obs, HID, nullptr, W_post, b_post, logits_out, LATD);
    sample_kernel<<<(BSZ * 32) / 256, 256>>>(logits_out, stoch_out);

    // ---- fp32 fix path for near-tie groups ----
    gather_rows<<<256, 256>>>(stoch, deter, action, obs, first);
    gemm_f32<<<dim3(HID / GBN, FIX_ROWS / GBM), dim3(256)>>>(
        fin, 1088, fin, 0, W_in, b_in, fx, HID);
    gemm_f32<<<dim3(3 * REC / GBN, FIX_ROWS / GBM), dim3(256)>>>(
        fx, 1024, fx, 0, W_ih, b_ih, fgi, 3 * REC);
    gemm_f32<<<dim3(3 * REC / GBN, FIX_ROWS / GBM), dim3(256)>>>(
        fdet, 1024, fdet, 0, W_hh, b_hh, fgh, 3 * REC);
    fgru_kernel<<<(FIX_ROWS * 1024) / 256, 256>>>();
    gemm_f32<<<dim3(LATD / GBN, FIX_ROWS / GBM), dim3(256)>>>(
        fh, 1024, fobs, 1024, W_post, b_post, flog, LATD);
    fix_sample<<<(FIX_ROWS * 32) / 256, 256>>>(stoch_out);
}